// round 14
// baseline (speedup 1.0000x reference)
#include <cuda_runtime.h>
#include <cuda_fp16.h>
#include <cstdint>

// Problem constants
#define N_NODES 100000
#define N_PAD   100096          // 782 * 128
#define NB1     100352          // per-relation bins padded to 98*1024
#define NBLK1   98              // NB1 / 1024
#define D 128
#define N_REL 4
#define N_EDGES 500000
#define TOT_E   (N_REL * N_EDGES)   // 2,000,000
#define KROW    512             // S row: [S0|S1|S2|S3] halves

// Device scratch (globals; zero-initialized at load; no runtime allocation)
__device__ __half g_Xs[(size_t)N_PAD * 128];         // x rows fp16 (padded)
__device__ __half g_S[(size_t)N_PAD * KROW];         // aggregated features per node
__device__ __half g_Wx[(size_t)128 * 640];           // [W0|W1|W2|W3|Wsl] per out-feature row
__device__ float g_C4[(size_t)N_NODES * 4];          // per-(node,rel) edge counts
__device__ int g_cnt[N_REL * NB1];                   // per-relation histograms (re-zeroed)
__device__ int g_off[N_REL * NB1];
__device__ int g_cursor[N_REL * NB1];
__device__ int g_part[N_REL * NBLK1];
__device__ int g_payload[TOT_E];                     // src node; relation r owns [r*5e5,(r+1)*5e5)

// ---------------------------------------------------------------------------
// helpers
// ---------------------------------------------------------------------------
__device__ __forceinline__ uint32_t smem_u32(const void* p) {
    uint32_t a;
    asm("{ .reg .u64 t; cvta.to.shared.u64 t, %1; cvt.u32.u64 %0, t; }" : "=r"(a) : "l"(p));
    return a;
}
__device__ __forceinline__ void ldsm_x4(uint32_t addr, uint32_t& r0, uint32_t& r1,
                                        uint32_t& r2, uint32_t& r3) {
    asm volatile("ldmatrix.sync.aligned.m8n8.x4.shared.b16 {%0,%1,%2,%3}, [%4];"
                 : "=r"(r0), "=r"(r1), "=r"(r2), "=r"(r3) : "r"(addr));
}
__device__ __forceinline__ void mma16816(float* c, uint32_t a0, uint32_t a1, uint32_t a2,
                                         uint32_t a3, uint32_t b0, uint32_t b1) {
    asm volatile("mma.sync.aligned.m16n8k16.row.col.f32.f16.f16.f32 "
                 "{%0,%1,%2,%3}, {%4,%5,%6,%7}, {%8,%9}, {%0,%1,%2,%3};"
                 : "+f"(c[0]), "+f"(c[1]), "+f"(c[2]), "+f"(c[3])
                 : "r"(a0), "r"(a1), "r"(a2), "r"(a3), "r"(b0), "r"(b1));
}
__device__ __forceinline__ void cp16(uint32_t smem_dst, const void* gsrc) {
    asm volatile("cp.async.cg.shared.global [%0], [%1], 16;"
                 :: "r"(smem_dst), "l"(gsrc));
}

// ---------------------------------------------------------------------------
// conversions
// ---------------------------------------------------------------------------
__global__ __launch_bounds__(256) void conv_x_kernel(const float* __restrict__ x) {
    size_t i = (size_t)blockIdx.x * blockDim.x + threadIdx.x;
    if (i >= (size_t)N_NODES * 32) return;
    size_t row = i >> 5;
    int c4 = (int)(i & 31);
    float4 v = reinterpret_cast<const float4*>(x)[i];
    __half h[4];
    h[0] = __float2half_rn(v.x); h[1] = __float2half_rn(v.y);
    h[2] = __float2half_rn(v.z); h[3] = __float2half_rn(v.w);
    *reinterpret_cast<uint2*>(&g_Xs[row * 128 + c4 * 4]) = *reinterpret_cast<uint2*>(h);
}

__global__ __launch_bounds__(256) void conv_w_kernel(const float* __restrict__ W,
                                                     const float* __restrict__ Wsl) {
    int i = blockIdx.x * blockDim.x + threadIdx.x;
    if (i >= 128 * 160) return;
    int f = i / 160;
    int c = (i - f * 160) * 4;
    float4 v;
    if (c < 512) {
        int r = c >> 7, dd = c & 127;
        v = *reinterpret_cast<const float4*>(W + (size_t)r * 16384 + (size_t)f * 128 + dd);
    } else {
        v = *reinterpret_cast<const float4*>(Wsl + (size_t)f * 128 + (c - 512));
    }
    __half h[4];
    h[0] = __float2half_rn(v.x); h[1] = __float2half_rn(v.y);
    h[2] = __float2half_rn(v.z); h[3] = __float2half_rn(v.w);
    *reinterpret_cast<uint2*>(&g_Wx[(size_t)f * 640 + c]) = *reinterpret_cast<uint2*>(h);
}

// ---------------------------------------------------------------------------
// Per-relation counting sort (key = tgt). Relation r passed as kernel arg.
// ---------------------------------------------------------------------------
__global__ __launch_bounds__(256) void hist_r_kernel(const int* __restrict__ EI, int r) {
    int i = blockIdx.x * blockDim.x + threadIdx.x;   // quad index within relation
    if (i >= N_EDGES / 4) return;
    int e = i * 4;
    int4 tg = *reinterpret_cast<const int4*>(EI + (size_t)r * 2 * N_EDGES + N_EDGES + e);
    int* cnt = g_cnt + r * NB1;
    atomicAdd(&cnt[tg.x], 1);
    atomicAdd(&cnt[tg.y], 1);
    atomicAdd(&cnt[tg.z], 1);
    atomicAdd(&cnt[tg.w], 1);
}

__global__ __launch_bounds__(256) void scan_part_r_kernel(int r) {
    __shared__ int s[256];
    int b = blockIdx.x, t = threadIdx.x;
    int4 v4 = reinterpret_cast<const int4*>(g_cnt + r * NB1)[b * 256 + t];
    s[t] = v4.x + v4.y + v4.z + v4.w;
    __syncthreads();
    for (int off = 128; off > 0; off >>= 1) {
        if (t < off) s[t] += s[t + off];
        __syncthreads();
    }
    if (t == 0) g_part[r * NBLK1 + b] = s[0];
}

__global__ __launch_bounds__(256) void scan_final_r_kernel(int r) {
    __shared__ int parts[NBLK1];
    __shared__ int s[256];
    int b = blockIdx.x, t = threadIdx.x;
    if (t < NBLK1) parts[t] = g_part[r * NBLK1 + t];
    __syncthreads();
    int pp = 0;
    if (t < b) pp = parts[t];           // b <= 97 < 256: one element per thread
    s[t] = pp;
    __syncthreads();
    for (int off = 128; off > 0; off >>= 1) {
        if (t < off) s[t] += s[t + off];
        __syncthreads();
    }
    const int blockbase = s[0] + r * N_EDGES;   // relation r's payload region base
    __syncthreads();

    int base = r * NB1 + b * 1024 + t * 4;
    int4 e4 = *reinterpret_cast<const int4*>(g_cnt + base);
    *reinterpret_cast<int4*>(g_cnt + base) = make_int4(0, 0, 0, 0);  // re-zero for replay
    int e[4] = {e4.x, e4.y, e4.z, e4.w};
    int local[4], sum = 0;
#pragma unroll
    for (int j = 0; j < 4; j++) { local[j] = sum; sum += e[j]; }
    s[t] = sum;
    __syncthreads();
    int own = sum;
    for (int d = 1; d < 256; d <<= 1) {
        int add = (t >= d) ? s[t - d] : 0;
        __syncthreads();
        s[t] += add;
        __syncthreads();
    }
    int baseoff = blockbase + (s[t] - own);
    int4 o4 = make_int4(baseoff + local[0], baseoff + local[1],
                        baseoff + local[2], baseoff + local[3]);
    *reinterpret_cast<int4*>(g_off + base) = o4;
    *reinterpret_cast<int4*>(g_cursor + base) = o4;
}

__global__ __launch_bounds__(256) void reorder_r_kernel(const int* __restrict__ EI, int r) {
    int i = blockIdx.x * blockDim.x + threadIdx.x;
    if (i >= N_EDGES / 4) return;
    int e = i * 4;
    const int* base = EI + (size_t)r * 2 * N_EDGES;
    int4 sr = *reinterpret_cast<const int4*>(base + e);
    int4 tg = *reinterpret_cast<const int4*>(base + N_EDGES + e);
    int* cur = g_cursor + r * NB1;
    g_payload[atomicAdd(&cur[tg.x], 1)] = sr.x;
    g_payload[atomicAdd(&cur[tg.y], 1)] = sr.y;
    g_payload[atomicAdd(&cur[tg.z], 1)] = sr.z;
    g_payload[atomicAdd(&cur[tg.w], 1)] = sr.w;
}

// ---------------------------------------------------------------------------
// Per-relation gather: one warp per target. Half-warp per edge, 2 edges/step.
// ---------------------------------------------------------------------------
__global__ __launch_bounds__(256) void gather_r_kernel(int r) {
    const int t = blockIdx.x * 8 + (threadIdx.x >> 5);
    if (t >= N_NODES) return;
    const int lane = threadIdx.x & 31;
    const int group = lane >> 4;
    const int sub = lane & 15;

    const int* off = g_off + r * NB1;
    const int beg = off[t];
    const int end = off[t + 1];

    float acc[8];
#pragma unroll
    for (int i = 0; i < 8; i++) acc[i] = 0.0f;

    for (int base = beg; base < end; base += 32) {
        int i = base + lane;
        int p = (i < end) ? g_payload[i] : 0;
        int m = min(end - base, 32);
        for (int j = 0; j < m; j += 2) {
            int jj = j + group;
            int src = __shfl_sync(0xffffffffu, p, min(jj, m - 1));
            if (jj < m) {
                uint4 raw = *reinterpret_cast<const uint4*>(
                    g_Xs + (size_t)src * 128 + sub * 8);
                const __half2* h2 = reinterpret_cast<const __half2*>(&raw);
#pragma unroll
                for (int q = 0; q < 4; q++) {
                    float2 f = __half22float2(h2[q]);
                    acc[q * 2 + 0] += f.x;
                    acc[q * 2 + 1] += f.y;
                }
            }
        }
    }
#pragma unroll
    for (int i = 0; i < 8; i++) acc[i] += __shfl_xor_sync(0xffffffffu, acc[i], 16);

    if (group == 0) {
        __half h[8];
#pragma unroll
        for (int q = 0; q < 8; q++) h[q] = __float2half_rn(acc[q]);
        *reinterpret_cast<uint4*>(&g_S[(size_t)t * KROW + r * 128 + sub * 8]) =
            *reinterpret_cast<uint4*>(h);
    }
    if (lane == 0) g_C4[(size_t)t * 4 + r] = (float)(end - beg);
}

// ---------------------------------------------------------------------------
// GEMM (cp.async double-buffered): out = [S|x] @ Wx^T + Sum_r C4*b_r + bsl
// ---------------------------------------------------------------------------
__global__ __launch_bounds__(256, 2) void gemm_mma_kernel(const float* __restrict__ b,
                                                          const float* __restrict__ bsl,
                                                          float* __restrict__ out) {
    extern __shared__ __half smem[];
    const int tid = threadIdx.x;
    const int lane = tid & 31;
    const int wid = tid >> 5;
    const int wm = wid & 3;
    const int wn = wid >> 2;
    const int m0 = blockIdx.x * 128;

    float acc[2][8][4];
#pragma unroll
    for (int i = 0; i < 2; i++)
#pragma unroll
        for (int j = 0; j < 8; j++)
#pragma unroll
            for (int k = 0; k < 4; k++) acc[i][j][k] = 0.0f;

    const uint32_t sAu = smem_u32(smem);
    const uint32_t sBu = sAu + 2 * 16384;

    auto load_tiles = [&](int buf, int step) {
        const int kc = step * 64;
#pragma unroll
        for (int it = 0; it < 4; it++) {
            int idx = tid + it * 256;
            int row = idx >> 3;
            int ch = idx & 7;
            int sw = (ch ^ (row & 7)) << 4;
            const __half* srcA = (kc < 512)
                ? (g_S + (size_t)(m0 + row) * KROW + kc + ch * 8)
                : (g_Xs + (size_t)(m0 + row) * 128 + (kc - 512) + ch * 8);
            cp16(sAu + buf * 16384 + row * 128 + sw, srcA);
            cp16(sBu + buf * 16384 + row * 128 + sw,
                 g_Wx + (size_t)row * 640 + kc + ch * 8);
        }
        asm volatile("cp.async.commit_group;");
    };

    load_tiles(0, 0);

#pragma unroll 1
    for (int step = 0; step < 10; step++) {
        if (step < 9) {
            load_tiles((step + 1) & 1, step + 1);
            asm volatile("cp.async.wait_group 1;");
        } else {
            asm volatile("cp.async.wait_group 0;");
        }
        __syncthreads();

        const int boff = (step & 1) * 16384;
#pragma unroll
        for (int kq = 0; kq < 4; kq++) {
            uint32_t a[2][4];
#pragma unroll
            for (int mf = 0; mf < 2; mf++) {
                int row = wm * 32 + mf * 16 + (lane & 15);
                int kch = kq * 2 + (lane >> 4);
                uint32_t addr = sAu + boff + row * 128 + ((kch ^ (row & 7)) << 4);
                ldsm_x4(addr, a[mf][0], a[mf][1], a[mf][2], a[mf][3]);
            }
            uint32_t bb[8][2];
#pragma unroll
            for (int np = 0; np < 4; np++) {
                int n = wn * 64 + np * 16 + ((lane >> 4) << 3) + (lane & 7);
                int kch = kq * 2 + ((lane >> 3) & 1);
                uint32_t addr = sBu + boff + n * 128 + ((kch ^ (n & 7)) << 4);
                ldsm_x4(addr, bb[np * 2][0], bb[np * 2][1], bb[np * 2 + 1][0], bb[np * 2 + 1][1]);
            }
#pragma unroll
            for (int mf = 0; mf < 2; mf++)
#pragma unroll
                for (int nf = 0; nf < 8; nf++)
                    mma16816(acc[mf][nf], a[mf][0], a[mf][1], a[mf][2], a[mf][3],
                             bb[nf][0], bb[nf][1]);
        }
        __syncthreads();
    }

    const int r0 = lane >> 2;
    const int c0 = (lane & 3) * 2;
#pragma unroll
    for (int mf = 0; mf < 2; mf++) {
#pragma unroll
        for (int half = 0; half < 2; half++) {
            int gm = m0 + wm * 32 + mf * 16 + r0 + half * 8;
            if (gm >= N_NODES) continue;
            float4 c4 = *reinterpret_cast<const float4*>(g_C4 + (size_t)gm * 4);
            float* dst = out + (size_t)gm * 128 + wn * 64 + c0;
#pragma unroll
            for (int nf = 0; nf < 8; nf++) {
                int col = wn * 64 + c0 + nf * 8;
                float2 b0 = *reinterpret_cast<const float2*>(b + 0 * 128 + col);
                float2 b1 = *reinterpret_cast<const float2*>(b + 1 * 128 + col);
                float2 b2 = *reinterpret_cast<const float2*>(b + 2 * 128 + col);
                float2 b3 = *reinterpret_cast<const float2*>(b + 3 * 128 + col);
                float2 bs = *reinterpret_cast<const float2*>(bsl + col);
                float2 v;
                v.x = acc[mf][nf][half * 2] +
                      c4.x * b0.x + c4.y * b1.x + c4.z * b2.x + c4.w * b3.x + bs.x;
                v.y = acc[mf][nf][half * 2 + 1] +
                      c4.x * b0.y + c4.y * b1.y + c4.z * b2.y + c4.w * b3.y + bs.y;
                *reinterpret_cast<float2*>(dst + nf * 8) = v;
            }
        }
    }
}

// ---------------------------------------------------------------------------
extern "C" void kernel_launch(void* const* d_in, const int* in_sizes, int n_in,
                              void* d_out, int out_size) {
    const float* x   = (const float*)d_in[0];
    const int*   ei  = (const int*)  d_in[1];
    const float* W   = (const float*)d_in[2];
    const float* b   = (const float*)d_in[3];
    const float* Wsl = (const float*)d_in[4];
    const float* bsl = (const float*)d_in[5];
    float* out = (float*)d_out;

    const int GEMM_SMEM = 4 * 128 * 64 * (int)sizeof(__half);  // 64 KB
    const int QBLK = (N_EDGES / 4 + 255) / 256;                // 489

    static cudaStream_t s2 = nullptr, s3 = nullptr;
    static cudaEvent_t ev_fork = nullptr, ev_convx = nullptr, ev_join = nullptr;
    static cudaEvent_t ev_sort[N_REL] = {};
    static bool overlap_ok = false;
    static bool attr_done = false;
    if (!attr_done) {
        cudaFuncSetAttribute(gemm_mma_kernel,
                             cudaFuncAttributeMaxDynamicSharedMemorySize, GEMM_SMEM);
        attr_done = true;
    }
    if (!s2) {
        bool ok =
            (cudaStreamCreateWithFlags(&s2, cudaStreamNonBlocking) == cudaSuccess) &&
            (cudaStreamCreateWithFlags(&s3, cudaStreamNonBlocking) == cudaSuccess) &&
            (cudaEventCreateWithFlags(&ev_fork, cudaEventDisableTiming) == cudaSuccess) &&
            (cudaEventCreateWithFlags(&ev_convx, cudaEventDisableTiming) == cudaSuccess) &&
            (cudaEventCreateWithFlags(&ev_join, cudaEventDisableTiming) == cudaSuccess);
        for (int r = 0; r < N_REL && ok; r++)
            ok = (cudaEventCreateWithFlags(&ev_sort[r], cudaEventDisableTiming) == cudaSuccess);
        overlap_ok = ok;
    }

    if (!overlap_ok) {
        conv_x_kernel<<<(N_NODES * 32 + 255) / 256, 256>>>(x);
        conv_w_kernel<<<(128 * 160 + 255) / 256, 256>>>(W, Wsl);
        for (int r = 0; r < N_REL; r++) {
            hist_r_kernel<<<QBLK, 256>>>(ei, r);
            scan_part_r_kernel<<<NBLK1, 256>>>(r);
            scan_final_r_kernel<<<NBLK1, 256>>>(r);
            reorder_r_kernel<<<QBLK, 256>>>(ei, r);
            gather_r_kernel<<<(N_NODES + 7) / 8, 256>>>(r);
        }
        gemm_mma_kernel<<<782, 256, GEMM_SMEM>>>(b, bsl, out);
        return;
    }

    // fork
    cudaEventRecord(ev_fork, 0);
    cudaStreamWaitEvent(s2, ev_fork, 0);
    cudaStreamWaitEvent(s3, ev_fork, 0);

    // Stream 0: conversions
    conv_x_kernel<<<(N_NODES * 32 + 255) / 256, 256>>>(x);
    cudaEventRecord(ev_convx, 0);
    conv_w_kernel<<<(128 * 160 + 255) / 256, 256>>>(W, Wsl);

    // Stream s3 gathers need g_Xs
    cudaStreamWaitEvent(s3, ev_convx, 0);

    // Pipeline: sorts on s2, gathers on s3 as each relation's sort lands
    for (int r = 0; r < N_REL; r++) {
        hist_r_kernel<<<QBLK, 256, 0, s2>>>(ei, r);
        scan_part_r_kernel<<<NBLK1, 256, 0, s2>>>(r);
        scan_final_r_kernel<<<NBLK1, 256, 0, s2>>>(r);
        reorder_r_kernel<<<QBLK, 256, 0, s2>>>(ei, r);
        cudaEventRecord(ev_sort[r], s2);

        cudaStreamWaitEvent(s3, ev_sort[r], 0);
        gather_r_kernel<<<(N_NODES + 7) / 8, 256, 0, s3>>>(r);
    }
    cudaEventRecord(ev_join, s3);

    // Stream 0: single fused GEMM after all gathers
    cudaStreamWaitEvent(0, ev_join, 0);
    gemm_mma_kernel<<<782, 256, GEMM_SMEM, 0>>>(b, bsl, out);
}

// round 15
// speedup vs baseline: 1.0811x; 1.0811x over previous
#include <cuda_runtime.h>
#include <cuda_fp16.h>
#include <cstdint>

// Problem constants
#define N_NODES 100000
#define N_PAD   100096          // 782 * 128
#define NBINS   400000          // 4 * N_NODES
#define NT2     400384          // bins padded to 391*1024
#define NBLK2   391             // NT2 / 1024
#define D 128
#define N_REL 4
#define N_EDGES 500000
#define TOT_E   (N_REL * N_EDGES)   // 2,000,000
#define KROW    512             // S row: [S0|S1|S2|S3] halves (x handled separately)

// Device scratch (globals; zero-initialized at load; no runtime allocation)
__device__ __half g_Xs[(size_t)N_PAD * 128];         // x rows fp16 (padded)
__device__ __half g_S[(size_t)N_PAD * KROW];         // aggregated features per node (102MB)
__device__ __half g_Wx[(size_t)128 * 640];           // [W0|W1|W2|W3|Wsl] per out-feature row
__device__ float g_C4[NBINS];                        // per-(node,rel) edge counts
__device__ int g_cnt[NT2];                           // zeroed at load; re-zeroed by scan_final
__device__ int g_off[NT2];
__device__ int g_cursor[NT2];
__device__ int g_part[NBLK2];
__device__ int g_payload[TOT_E];                     // src node per sorted edge

// ---------------------------------------------------------------------------
// helpers
// ---------------------------------------------------------------------------
__device__ __forceinline__ uint32_t smem_u32(const void* p) {
    uint32_t a;
    asm("{ .reg .u64 t; cvta.to.shared.u64 t, %1; cvt.u32.u64 %0, t; }" : "=r"(a) : "l"(p));
    return a;
}
__device__ __forceinline__ void ldsm_x4(uint32_t addr, uint32_t& r0, uint32_t& r1,
                                        uint32_t& r2, uint32_t& r3) {
    asm volatile("ldmatrix.sync.aligned.m8n8.x4.shared.b16 {%0,%1,%2,%3}, [%4];"
                 : "=r"(r0), "=r"(r1), "=r"(r2), "=r"(r3) : "r"(addr));
}
__device__ __forceinline__ void mma16816(float* c, uint32_t a0, uint32_t a1, uint32_t a2,
                                         uint32_t a3, uint32_t b0, uint32_t b1) {
    asm volatile("mma.sync.aligned.m16n8k16.row.col.f32.f16.f16.f32 "
                 "{%0,%1,%2,%3}, {%4,%5,%6,%7}, {%8,%9}, {%0,%1,%2,%3};"
                 : "+f"(c[0]), "+f"(c[1]), "+f"(c[2]), "+f"(c[3])
                 : "r"(a0), "r"(a1), "r"(a2), "r"(a3), "r"(b0), "r"(b1));
}
__device__ __forceinline__ void cp16(uint32_t smem_dst, const void* gsrc) {
    asm volatile("cp.async.cg.shared.global [%0], [%1], 16;"
                 :: "r"(smem_dst), "l"(gsrc));
}

// ---------------------------------------------------------------------------
// conv: fp32 x -> fp16 g_Xs rows; blocks past the X range convert W/Wsl -> g_Wx
// ---------------------------------------------------------------------------
#define X_QUADS (N_NODES * 32)           // 3,200,000 float4s
#define W_QUADS (128 * 160)              // 20,480 float4s
#define CONV_BLOCKS ((X_QUADS + W_QUADS + 255) / 256)

__global__ __launch_bounds__(256) void conv_kernel(const float* __restrict__ x,
                                                   const float* __restrict__ W,
                                                   const float* __restrict__ Wsl) {
    size_t i = (size_t)blockIdx.x * blockDim.x + threadIdx.x;
    if (i < (size_t)X_QUADS) {
        size_t row = i >> 5;
        int c4 = (int)(i & 31);
        float4 v = reinterpret_cast<const float4*>(x)[i];
        __half h[4];
        h[0] = __float2half_rn(v.x); h[1] = __float2half_rn(v.y);
        h[2] = __float2half_rn(v.z); h[3] = __float2half_rn(v.w);
        *reinterpret_cast<uint2*>(&g_Xs[row * 128 + c4 * 4]) = *reinterpret_cast<uint2*>(h);
    } else {
        int j = (int)(i - X_QUADS);
        if (j >= W_QUADS) return;
        int f = j / 160;
        int c = (j - f * 160) * 4;
        float4 v;
        if (c < 512) {
            int r = c >> 7, dd = c & 127;
            v = *reinterpret_cast<const float4*>(W + (size_t)r * 16384 + (size_t)f * 128 + dd);
        } else {
            v = *reinterpret_cast<const float4*>(Wsl + (size_t)f * 128 + (c - 512));
        }
        __half h[4];
        h[0] = __float2half_rn(v.x); h[1] = __float2half_rn(v.y);
        h[2] = __float2half_rn(v.z); h[3] = __float2half_rn(v.w);
        *reinterpret_cast<uint2*>(&g_Wx[(size_t)f * 640 + c]) = *reinterpret_cast<uint2*>(h);
    }
}

// ---------------------------------------------------------------------------
// Counting sort by key = tgt*4 + rel  (vectorized, 4 edges/thread)
// g_cnt starts zero (load-time init); scan_final re-zeros it after reading.
// ---------------------------------------------------------------------------
__global__ __launch_bounds__(256) void hist_kernel(const int* __restrict__ EI) {
    int i = blockIdx.x * blockDim.x + threadIdx.x;
    if (i >= TOT_E / 4) return;
    int gq = i * 4;
    int r = gq / N_EDGES;
    int e = gq - r * N_EDGES;
    int4 tg = *reinterpret_cast<const int4*>(EI + (size_t)r * 2 * N_EDGES + N_EDGES + e);
    atomicAdd(&g_cnt[tg.x * 4 + r], 1);
    atomicAdd(&g_cnt[tg.y * 4 + r], 1);
    atomicAdd(&g_cnt[tg.z * 4 + r], 1);
    atomicAdd(&g_cnt[tg.w * 4 + r], 1);
}

__global__ __launch_bounds__(256) void scan_part_kernel() {
    __shared__ int s[256];
    int b = blockIdx.x, t = threadIdx.x;
    int4 v4 = reinterpret_cast<const int4*>(g_cnt)[b * 256 + t];
    s[t] = v4.x + v4.y + v4.z + v4.w;
    __syncthreads();
    for (int off = 128; off > 0; off >>= 1) {
        if (t < off) s[t] += s[t + off];
        __syncthreads();
    }
    if (t == 0) g_part[b] = s[0];
}

__global__ __launch_bounds__(256) void scan_final_kernel() {
    __shared__ int parts[NBLK2];
    __shared__ int s[256];
    int b = blockIdx.x, t = threadIdx.x;
    for (int i = t; i < NBLK2; i += 256) parts[i] = g_part[i];
    __syncthreads();
    int pp = 0;
    for (int i = t; i < b; i += 256) pp += parts[i];
    s[t] = pp;
    __syncthreads();
    for (int off = 128; off > 0; off >>= 1) {
        if (t < off) s[t] += s[t + off];
        __syncthreads();
    }
    const int blockbase = s[0];
    __syncthreads();

    int base = b * 1024 + t * 4;
    int4 e4 = *reinterpret_cast<const int4*>(g_cnt + base);
    *reinterpret_cast<int4*>(g_cnt + base) = make_int4(0, 0, 0, 0);  // re-zero for replay
    int e[4] = {e4.x, e4.y, e4.z, e4.w};
    int local[4], sum = 0;
#pragma unroll
    for (int j = 0; j < 4; j++) { local[j] = sum; sum += e[j]; }
    s[t] = sum;
    __syncthreads();
    int own = sum;
    for (int d = 1; d < 256; d <<= 1) {
        int add = (t >= d) ? s[t - d] : 0;
        __syncthreads();
        s[t] += add;
        __syncthreads();
    }
    int baseoff = blockbase + (s[t] - own);
    int4 o4 = make_int4(baseoff + local[0], baseoff + local[1],
                        baseoff + local[2], baseoff + local[3]);
    *reinterpret_cast<int4*>(g_off + base) = o4;
    *reinterpret_cast<int4*>(g_cursor + base) = o4;
}

__global__ __launch_bounds__(256) void reorder_kernel(const int* __restrict__ EI) {
    int i = blockIdx.x * blockDim.x + threadIdx.x;
    if (i >= TOT_E / 4) return;
    int gq = i * 4;
    int r = gq / N_EDGES;
    int e = gq - r * N_EDGES;
    const int* base = EI + (size_t)r * 2 * N_EDGES;
    int4 sr = *reinterpret_cast<const int4*>(base + e);
    int4 tg = *reinterpret_cast<const int4*>(base + N_EDGES + e);
    g_payload[atomicAdd(&g_cursor[tg.x * 4 + r], 1)] = sr.x;
    g_payload[atomicAdd(&g_cursor[tg.y * 4 + r], 1)] = sr.y;
    g_payload[atomicAdd(&g_cursor[tg.z * 4 + r], 1)] = sr.z;
    g_payload[atomicAdd(&g_cursor[tg.w * 4 + r], 1)] = sr.w;
}

// ---------------------------------------------------------------------------
// Gather: one warp per (target,rel) BIN. k = t*4+r. Mean 5 edges/bin.
// Half-warp per edge (16 lanes x 16B), two edges per step. (Proven form.)
// ---------------------------------------------------------------------------
__global__ __launch_bounds__(256) void gather_kernel() {
    const int k = blockIdx.x * 8 + (threadIdx.x >> 5);
    if (k >= NBINS) return;
    const int lane = threadIdx.x & 31;
    const int group = lane >> 4;
    const int sub = lane & 15;

    const int beg = g_off[k];
    const int end = g_off[k + 1];

    float acc[8];
#pragma unroll
    for (int i = 0; i < 8; i++) acc[i] = 0.0f;

    for (int base = beg; base < end; base += 32) {
        int i = base + lane;
        int p = (i < end) ? g_payload[i] : 0;
        int m = min(end - base, 32);
        for (int j = 0; j < m; j += 2) {
            int jj = j + group;
            int src = __shfl_sync(0xffffffffu, p, min(jj, m - 1));
            if (jj < m) {
                uint4 raw = *reinterpret_cast<const uint4*>(
                    g_Xs + (size_t)src * 128 + sub * 8);
                const __half2* h2 = reinterpret_cast<const __half2*>(&raw);
#pragma unroll
                for (int q = 0; q < 4; q++) {
                    float2 f = __half22float2(h2[q]);
                    acc[q * 2 + 0] += f.x;
                    acc[q * 2 + 1] += f.y;
                }
            }
        }
    }
#pragma unroll
    for (int i = 0; i < 8; i++) acc[i] += __shfl_xor_sync(0xffffffffu, acc[i], 16);

    if (group == 0) {
        const int t = k >> 2;
        const int r = k & 3;
        __half h[8];
#pragma unroll
        for (int q = 0; q < 8; q++) h[q] = __float2half_rn(acc[q]);
        *reinterpret_cast<uint4*>(&g_S[(size_t)t * KROW + r * 128 + sub * 8]) =
            *reinterpret_cast<uint4*>(h);
    }
    if (lane == 0) g_C4[k] = (float)(end - beg);
}

// ---------------------------------------------------------------------------
// GEMM (cp.async double-buffered): out = [S|x] @ Wx^T + Sum_r C4*b_r + bsl
// K=640: steps 0..7 read g_S (512 cols), steps 8..9 read g_Xs (128 cols).
// ---------------------------------------------------------------------------
__global__ __launch_bounds__(256, 2) void gemm_mma_kernel(const float* __restrict__ b,
                                                          const float* __restrict__ bsl,
                                                          float* __restrict__ out) {
    extern __shared__ __half smem[];
    const int tid = threadIdx.x;
    const int lane = tid & 31;
    const int wid = tid >> 5;
    const int wm = wid & 3;
    const int wn = wid >> 2;
    const int m0 = blockIdx.x * 128;

    float acc[2][8][4];
#pragma unroll
    for (int i = 0; i < 2; i++)
#pragma unroll
        for (int j = 0; j < 8; j++)
#pragma unroll
            for (int k = 0; k < 4; k++) acc[i][j][k] = 0.0f;

    const uint32_t sAu = smem_u32(smem);
    const uint32_t sBu = sAu + 2 * 16384;

    auto load_tiles = [&](int buf, int step) {
        const int kc = step * 64;
#pragma unroll
        for (int it = 0; it < 4; it++) {
            int idx = tid + it * 256;
            int row = idx >> 3;
            int ch = idx & 7;
            int sw = (ch ^ (row & 7)) << 4;
            const __half* srcA = (kc < 512)
                ? (g_S + (size_t)(m0 + row) * KROW + kc + ch * 8)
                : (g_Xs + (size_t)(m0 + row) * 128 + (kc - 512) + ch * 8);
            cp16(sAu + buf * 16384 + row * 128 + sw, srcA);
            cp16(sBu + buf * 16384 + row * 128 + sw,
                 g_Wx + (size_t)row * 640 + kc + ch * 8);
        }
        asm volatile("cp.async.commit_group;");
    };

    load_tiles(0, 0);

#pragma unroll 1
    for (int step = 0; step < 10; step++) {
        if (step < 9) {
            load_tiles((step + 1) & 1, step + 1);
            asm volatile("cp.async.wait_group 1;");
        } else {
            asm volatile("cp.async.wait_group 0;");
        }
        __syncthreads();

        const int boff = (step & 1) * 16384;
#pragma unroll
        for (int kq = 0; kq < 4; kq++) {
            uint32_t a[2][4];
#pragma unroll
            for (int mf = 0; mf < 2; mf++) {
                int row = wm * 32 + mf * 16 + (lane & 15);
                int kch = kq * 2 + (lane >> 4);
                uint32_t addr = sAu + boff + row * 128 + ((kch ^ (row & 7)) << 4);
                ldsm_x4(addr, a[mf][0], a[mf][1], a[mf][2], a[mf][3]);
            }
            uint32_t bb[8][2];
#pragma unroll
            for (int np = 0; np < 4; np++) {
                int n = wn * 64 + np * 16 + ((lane >> 4) << 3) + (lane & 7);
                int kch = kq * 2 + ((lane >> 3) & 1);
                uint32_t addr = sBu + boff + n * 128 + ((kch ^ (n & 7)) << 4);
                ldsm_x4(addr, bb[np * 2][0], bb[np * 2][1], bb[np * 2 + 1][0], bb[np * 2 + 1][1]);
            }
#pragma unroll
            for (int mf = 0; mf < 2; mf++)
#pragma unroll
                for (int nf = 0; nf < 8; nf++)
                    mma16816(acc[mf][nf], a[mf][0], a[mf][1], a[mf][2], a[mf][3],
                             bb[nf][0], bb[nf][1]);
        }
        __syncthreads();
    }

    const int r0 = lane >> 2;
    const int c0 = (lane & 3) * 2;
#pragma unroll
    for (int mf = 0; mf < 2; mf++) {
#pragma unroll
        for (int half = 0; half < 2; half++) {
            int gm = m0 + wm * 32 + mf * 16 + r0 + half * 8;
            if (gm >= N_NODES) continue;
            float4 c4 = *reinterpret_cast<const float4*>(g_C4 + (size_t)gm * 4);
            float* dst = out + (size_t)gm * 128 + wn * 64 + c0;
#pragma unroll
            for (int nf = 0; nf < 8; nf++) {
                int col = wn * 64 + c0 + nf * 8;
                float2 b0 = *reinterpret_cast<const float2*>(b + 0 * 128 + col);
                float2 b1 = *reinterpret_cast<const float2*>(b + 1 * 128 + col);
                float2 b2 = *reinterpret_cast<const float2*>(b + 2 * 128 + col);
                float2 b3 = *reinterpret_cast<const float2*>(b + 3 * 128 + col);
                float2 bs = *reinterpret_cast<const float2*>(bsl + col);
                float2 v;
                v.x = acc[mf][nf][half * 2] +
                      c4.x * b0.x + c4.y * b1.x + c4.z * b2.x + c4.w * b3.x + bs.x;
                v.y = acc[mf][nf][half * 2 + 1] +
                      c4.x * b0.y + c4.y * b1.y + c4.z * b2.y + c4.w * b3.y + bs.y;
                *reinterpret_cast<float2*>(dst + nf * 8) = v;
            }
        }
    }
}

// ---------------------------------------------------------------------------
extern "C" void kernel_launch(void* const* d_in, const int* in_sizes, int n_in,
                              void* d_out, int out_size) {
    const float* x   = (const float*)d_in[0];
    const int*   ei  = (const int*)  d_in[1];
    const float* W   = (const float*)d_in[2];
    const float* b   = (const float*)d_in[3];
    const float* Wsl = (const float*)d_in[4];
    const float* bsl = (const float*)d_in[5];
    float* out = (float*)d_out;

    const int GEMM_SMEM = 4 * 128 * 64 * (int)sizeof(__half);  // 64 KB

    static cudaStream_t s2 = nullptr;
    static cudaEvent_t ev_fork = nullptr, ev_conv = nullptr, ev_join = nullptr;
    static bool overlap_ok = false;
    static bool attr_done = false;
    if (!attr_done) {
        cudaFuncSetAttribute(gemm_mma_kernel,
                             cudaFuncAttributeMaxDynamicSharedMemorySize, GEMM_SMEM);
        attr_done = true;
    }
    if (!s2) {
        overlap_ok =
            (cudaStreamCreateWithFlags(&s2, cudaStreamNonBlocking) == cudaSuccess) &&
            (cudaEventCreateWithFlags(&ev_fork, cudaEventDisableTiming) == cudaSuccess) &&
            (cudaEventCreateWithFlags(&ev_conv, cudaEventDisableTiming) == cudaSuccess) &&
            (cudaEventCreateWithFlags(&ev_join, cudaEventDisableTiming) == cudaSuccess);
    }

    if (!overlap_ok) {
        conv_kernel<<<CONV_BLOCKS, 256>>>(x, W, Wsl);
        hist_kernel<<<(TOT_E / 4 + 255) / 256, 256>>>(ei);
        scan_part_kernel<<<NBLK2, 256>>>();
        scan_final_kernel<<<NBLK2, 256>>>();
        reorder_kernel<<<(TOT_E / 4 + 255) / 256, 256>>>(ei);
        gather_kernel<<<NBINS / 8, 256>>>();
        gemm_mma_kernel<<<782, 256, GEMM_SMEM>>>(b, bsl, out);
        return;
    }

    // fork
    cudaEventRecord(ev_fork, 0);
    cudaStreamWaitEvent(s2, ev_fork, 0);

    // Stream 0: conversions (x -> g_Xs, W/Wsl -> g_Wx) in one launch
    conv_kernel<<<CONV_BLOCKS, 256>>>(x, W, Wsl);
    cudaEventRecord(ev_conv, 0);

    // Stream B: counting sort, then gather (needs g_Xs)
    hist_kernel<<<(TOT_E / 4 + 255) / 256, 256, 0, s2>>>(ei);
    scan_part_kernel<<<NBLK2, 256, 0, s2>>>();
    scan_final_kernel<<<NBLK2, 256, 0, s2>>>();
    reorder_kernel<<<(TOT_E / 4 + 255) / 256, 256, 0, s2>>>(ei);
    cudaStreamWaitEvent(s2, ev_conv, 0);
    gather_kernel<<<NBINS / 8, 256, 0, s2>>>();
    cudaEventRecord(ev_join, s2);

    // Stream 0: single fused GEMM after gather
    cudaStreamWaitEvent(0, ev_join, 0);
    gemm_mma_kernel<<<782, 256, GEMM_SMEM, 0>>>(b, bsl, out);
}